// round 3
// baseline (speedup 1.0000x reference)
#include <cuda_runtime.h>
#include <cstdint>

// Fused: out[o*256+k][h][m] = sum_{i,j} w[i][k][j] * pad(xroll)[m+j]
// Grid = 224 blocks x 128 threads: bx -> (ich: 4, okt: 4, h: 14).
// Each block computes a 64-i partial for its (o, k-tile, h) slice with f32x2 FMAs,
// writes it to __device__ scratch; the last of the 4 ich-blocks per (okt,h) group
// reduces in fixed ich order (deterministic) and writes d_out.

#define ILEN 64

__device__ float g_partial[4 * 512 * 196];
__device__ unsigned int g_cnt[56];   // zero-init at load; reducer resets -> replay-safe

__device__ __forceinline__ uint64_t pk2(float lo, float hi) {
    uint64_t r;
    asm("mov.b64 %0, {%1, %2};" : "=l"(r) : "r"(__float_as_uint(lo)), "r"(__float_as_uint(hi)));
    return r;
}
__device__ __forceinline__ uint64_t ffma2(uint64_t a, uint64_t b, uint64_t c) {
    uint64_t d;
    asm("fma.rn.f32x2 %0, %1, %2, %3;" : "=l"(d) : "l"(a), "l"(b), "l"(c));
    return d;
}

__global__ __launch_bounds__(128) void fused_conv_kernel(const float* __restrict__ x,
                                                         const float* __restrict__ w,
                                                         float* __restrict__ out) {
    const int bx  = blockIdx.x;        // 0..223
    const int ich = bx & 3;
    const int okt = (bx >> 2) & 3;
    const int h   = bx >> 4;           // 0..13
    const int grp = bx >> 2;           // (okt,h) group, 0..55
    const int o   = okt >> 1;
    const int kt  = okt & 1;
    const int tx  = threadIdx.x;
    const int k   = kt * 128 + tx;
    const int n   = (h + 13) % 14;     // undo roll along H

    // sxe[il][mm] = zero-padded, W-rolled row at tap mm; sxo = shifted by +1 (odd pairs)
    __shared__ float sxe[ILEN][16];
    __shared__ float sxo[ILEN][16];
    __shared__ int s_last;

    const float* xrow = x + ((size_t)(o * 256 + ich * ILEN) * 14 + n) * 14;
    for (int idx = tx; idx < ILEN * 16; idx += 128) {
        const int il = idx >> 4;
        const int mm = idx & 15;
        float ve = 0.f, vo = 0.f;
        if (mm >= 1 && mm <= 14) ve = xrow[(size_t)il * 196 + (mm + 12) % 14];
        if (mm <= 13)            vo = xrow[(size_t)il * 196 + (mm + 13) % 14];
        sxe[il][mm] = ve;
        sxo[il][mm] = vo;
    }
    __syncthreads();

    uint64_t A[7];
#pragma unroll
    for (int p = 0; p < 7; p++) A[p] = 0ull;

    const float* wp = w + ((size_t)(ich * ILEN) * 256 + k) * 3;

#pragma unroll 8
    for (int il = 0; il < ILEN; ++il) {
        const float w0 = wp[0];
        const float w1 = wp[1];
        const float w2 = wp[2];
        wp += 256 * 3;
        const uint64_t W0 = pk2(w0, w0);
        const uint64_t W1 = pk2(w1, w1);
        const uint64_t W2 = pk2(w2, w2);

        const ulonglong2 e01 = *(const ulonglong2*)&sxe[il][0];
        const ulonglong2 e23 = *(const ulonglong2*)&sxe[il][4];
        const ulonglong2 e45 = *(const ulonglong2*)&sxe[il][8];
        const ulonglong2 e67 = *(const ulonglong2*)&sxe[il][12];
        const ulonglong2 o01 = *(const ulonglong2*)&sxo[il][0];
        const ulonglong2 o23 = *(const ulonglong2*)&sxo[il][4];
        const ulonglong2 o45 = *(const ulonglong2*)&sxo[il][8];
        const ulonglong2 o6_ = *(const ulonglong2*)&sxo[il][12];

        uint64_t E[8] = {e01.x, e01.y, e23.x, e23.y, e45.x, e45.y, e67.x, e67.y};
        uint64_t O[7] = {o01.x, o01.y, o23.x, o23.y, o45.x, o45.y, o6_.x};

#pragma unroll
        for (int p = 0; p < 7; p++) {
            A[p] = ffma2(W0, E[p],     A[p]);
            A[p] = ffma2(W1, O[p],     A[p]);
            A[p] = ffma2(W2, E[p + 1], A[p]);
        }
    }

    // partial layout: [ich][c][196], c = o*256+k; per-thread 14 contiguous floats
    {
        float* pp = g_partial + ((size_t)ich * 512 + o * 256 + k) * 196 + h * 14;
#pragma unroll
        for (int p = 0; p < 7; p++)
            *(uint64_t*)&pp[2 * p] = A[p];
    }

    // ---- last-block-done reduction for this (okt, h) group ----
    __threadfence();                       // release partials
    if (tx == 0) {
        unsigned int old = atomicAdd(&g_cnt[grp], 1u);
        s_last = (old == 3u);
    }
    __syncthreads();
    if (s_last) {
        __threadfence();                   // acquire: see all 4 ich partials
        const size_t off = ((size_t)(o * 256 + k)) * 196 + h * 14;
        const float* p0 = g_partial + off;
        const float* p1 = p0 + 1 * 512 * 196;
        const float* p2 = p0 + 2 * 512 * 196;
        const float* p3 = p0 + 3 * 512 * 196;
        float* op = out + off;
#pragma unroll
        for (int p = 0; p < 7; p++) {
            const float2 a = *(const float2*)&p0[2 * p];
            const float2 b = *(const float2*)&p1[2 * p];
            const float2 c = *(const float2*)&p2[2 * p];
            const float2 d = *(const float2*)&p3[2 * p];
            float2 s;
            s.x = ((a.x + b.x) + c.x) + d.x;   // fixed order -> deterministic
            s.y = ((a.y + b.y) + c.y) + d.y;
            *(float2*)&op[2 * p] = s;
        }
        if (tx == 0) g_cnt[grp] = 0u;      // reset for next graph replay
    }
}

extern "C" void kernel_launch(void* const* d_in, const int* in_sizes, int n_in,
                              void* d_out, int out_size) {
    const float* x = (const float*)d_in[0];   // (1,512,14,14)
    const float* w = (const float*)d_in[1];   // (256,256,3)
    float* out = (float*)d_out;

    fused_conv_kernel<<<224, 128>>>(x, w, out);
}